// round 9
// baseline (speedup 1.0000x reference)
#include <cuda_runtime.h>

#define BB   2
#define NN   16384
#define MM   4096
#define CF   256
#define CT   128
#define CP   64
#define CTOT 384
#define PTS  16
#define G    32
#define GC   (G * G * G)
#define HCELL 0.25f
#define ORG  (-4.0f)
#define INVH 4.0f

// ---- scratch (device globals; no allocation allowed) ----------------------
__device__ int    g_rcnt[BB][GC];
__device__ int    g_qcnt[BB][GC];
__device__ int    g_rstart[BB][GC + 1];
__device__ int    g_qstart[BB][GC + 1];
__device__ int    g_rcur[BB][GC];
__device__ int    g_qcur[BB][GC];
__device__ float4 g_rsort[BB * MM];
__device__ int    g_rid[BB * MM];
__device__ float4 g_qsort[BB * NN];
__device__ int    g_qid[BB * NN];
__device__ int    g_idx[BB * NN * 3];
__device__ float  g_w[BB * NN * 3];
__device__ float  g_featT[(size_t)BB * MM * CTOT];

__device__ __forceinline__ int cell1(float x) {
    int c = (int)floorf((x - ORG) * INVH);
    return min(max(c, 0), G - 1);
}

#define INS3(d0, d1, d2, i0, i1, i2, dv, iv)                                   \
    if (dv < d2) {                                                             \
        if (dv < d1) {                                                         \
            d2 = d1; i2 = i1;                                                  \
            if (dv < d0) { d1 = d0; i1 = i0; d0 = dv; i0 = iv; }               \
            else         { d1 = dv; i1 = iv; }                                 \
        } else { d2 = dv; i2 = iv; }                                           \
    }

// ---------------------------------------------------------------------------
__global__ __launch_bounds__(256) void zero_kernel() {
    int i = blockIdx.x * 256 + threadIdx.x;          // over BB*GC
    ((int*)g_rcnt)[i] = 0;
    ((int*)g_qcnt)[i] = 0;
}

__global__ __launch_bounds__(256) void count_kernel(const float* __restrict__ coords,
                                                    const float* __restrict__ refc) {
    int i = blockIdx.x * 256 + threadIdx.x;
    const int nref = BB * MM;
    if (i < nref) {
        int b = i / MM;
        const float* r = refc + (size_t)i * 3;
        int c = (cell1(r[2]) * G + cell1(r[1])) * G + cell1(r[0]);
        atomicAdd(&g_rcnt[b][c], 1);
    } else if (i < nref + BB * NN) {
        int j = i - nref;
        int b = j / NN;
        const float* p = coords + (size_t)j * 3;
        int c = (cell1(p[2]) * G + cell1(p[1])) * G + cell1(p[0]);
        atomicAdd(&g_qcnt[b][c], 1);
    }
}

// one block per (batch, type): exclusive scan of 32768 counts
__global__ __launch_bounds__(1024) void scan_kernel() {
    int type = blockIdx.x & 1, b = blockIdx.x >> 1;
    const int* cnt = type ? g_qcnt[b] : g_rcnt[b];
    int* start = type ? g_qstart[b] : g_rstart[b];
    int* cur   = type ? g_qcur[b]   : g_rcur[b];

    int t = threadIdx.x, lane = t & 31, w = t >> 5;
    int base = t * 32;
    int loc[32];
    int s = 0;
    #pragma unroll
    for (int i = 0; i < 32; i++) { loc[i] = s; s += cnt[base + i]; }

    int inc = s;
    #pragma unroll
    for (int off = 1; off < 32; off <<= 1) {
        int v = __shfl_up_sync(0xffffffffu, inc, off);
        if (lane >= off) inc += v;
    }
    __shared__ int wsum[32];
    if (lane == 31) wsum[w] = inc;
    __syncthreads();
    if (w == 0) {
        int v = wsum[lane];
        #pragma unroll
        for (int off = 1; off < 32; off <<= 1) {
            int u = __shfl_up_sync(0xffffffffu, v, off);
            if (lane >= off) v += u;
        }
        wsum[lane] = v;
    }
    __syncthreads();
    int myoff = inc - s + (w ? wsum[w - 1] : 0);
    #pragma unroll
    for (int i = 0; i < 32; i++) {
        start[base + i] = myoff + loc[i];
        cur[base + i]   = myoff + loc[i];
    }
    if (t == 1023) start[GC] = myoff + s;
}

__global__ __launch_bounds__(256) void scatter_kernel(const float* __restrict__ coords,
                                                      const float* __restrict__ refc) {
    int i = blockIdx.x * 256 + threadIdx.x;
    const int nref = BB * MM;
    if (i < nref) {
        int b = i / MM;
        const float* r = refc + (size_t)i * 3;
        float x = r[0], y = r[1], z = r[2];
        int c = (cell1(z) * G + cell1(y)) * G + cell1(x);
        int pos = atomicAdd(&g_rcur[b][c], 1);
        g_rsort[b * MM + pos] = make_float4(x, y, z, x * x + y * y + z * z);
        g_rid[b * MM + pos]   = i - b * MM;
    } else if (i < nref + BB * NN) {
        int j = i - nref;
        int b = j / NN;
        const float* p = coords + (size_t)j * 3;
        float x = p[0], y = p[1], z = p[2];
        int c = (cell1(z) * G + cell1(y)) * G + cell1(x);
        int pos = atomicAdd(&g_qcur[b][c], 1);
        g_qsort[b * NN + pos] = make_float4(x, y, z, x * x + y * y + z * z);
        g_qid[b * NN + pos]   = j - b * NN;
    }
}

// ---------------------------------------------------------------------------
// Exact 3-NN by expanding Chebyshev rings over the ref grid. One (sorted)
// query per lane; termination when the explored box's face distance beats
// the current 3rd-NN distance. Out-of-grid cells are empty = explored.
// (Clamped points lie OUTSIDE their border cell's box, i.e. farther than the
// box-face lower bound, so the termination test remains exact.)
// ---------------------------------------------------------------------------
__global__ __launch_bounds__(128) void knn_query_kernel() {
    int id = blockIdx.x * 128 + threadIdx.x;     // over BB*NN sorted queries
    int b = id / NN;

    float4 q = g_qsort[id];
    float px = q.x, py = q.y, pz = q.z, pp = q.w;
    float px2 = -2.0f * px, py2 = -2.0f * py, pz2 = -2.0f * pz;
    int cx = cell1(px), cy = cell1(py), cz = cell1(pz);

    float d0 = 1e30f, d1 = 1e30f, d2 = 1e30f;    // shifted: |r|^2 - 2 p.r
    int   i0 = 0, i1 = 0, i2 = 0;

    const int*    cs = g_rstart[b];
    const float4* rs = g_rsort + b * MM;

    for (int r = 0; r <= G; r++) {
        for (int dz = -r; dz <= r; dz++) {
            int z = cz + dz;
            if (z < 0 || z >= G) continue;
            bool zface = (dz == -r) || (dz == r);
            for (int dy = -r; dy <= r; dy++) {
                int y = cy + dy;
                if (y < 0 || y >= G) continue;
                bool face = zface || (dy == -r) || (dy == r);
                int step = face ? 1 : (r > 0 ? 2 * r : 1);
                for (int dx = -r; dx <= r; dx += step) {
                    int x = cx + dx;
                    if (x < 0 || x >= G) continue;
                    int cid = (z * G + y) * G + x;
                    int s = cs[cid], e = cs[cid + 1];
                    for (int j = s; j < e; j++) {
                        float4 rr = rs[j];
                        float dp = fmaf(rr.x, px2, fmaf(rr.y, py2, fmaf(rr.z, pz2, rr.w)));
                        INS3(d0, d1, d2, i0, i1, i2, dp, j);
                    }
                }
            }
        }
        // termination: explored box after ring r = [(c-r)h+ORG, (c+r+1)h+ORG]^3
        float mx = fminf(px - ((cx - r) * HCELL + ORG), ((cx + r + 1) * HCELL + ORG) - px);
        float my = fminf(py - ((cy - r) * HCELL + ORG), ((cy + r + 1) * HCELL + ORG) - py);
        float mz = fminf(pz - ((cz - r) * HCELL + ORG), ((cz + r + 1) * HCELL + ORG) - pz);
        float margin = fminf(mx, fminf(my, mz));
        if (margin > 0.0f && margin * margin >= d2 + pp) break;
    }

    float t0 = d0 + pp, t1 = d1 + pp, t2 = d2 + pp;
    float w0 = 1.0f / (t0 + 1e-8f);
    float w1 = 1.0f / (t1 + 1e-8f);
    float w2 = 1.0f / (t2 + 1e-8f);
    float inv = 1.0f / (w0 + w1 + w2);

    int outp = b * NN + g_qid[id];               // original query position
    size_t o = (size_t)outp * 3;
    g_w[o]     = w0 * inv;
    g_w[o + 1] = w1 * inv;
    g_w[o + 2] = w2 * inv;
    g_idx[o]     = g_rid[b * MM + i0];
    g_idx[o + 1] = g_rid[b * MM + i1];
    g_idx[o + 2] = g_rid[b * MM + i2];
}

// ---------------------------------------------------------------------------
// Transpose ref_features + ref_t_embed into channel-contiguous [B, M, 384].
// ---------------------------------------------------------------------------
__global__ __launch_bounds__(256) void transpose_kernel(const float* __restrict__ rf,
                                                        const float* __restrict__ rt) {
    __shared__ float tile[32][33];
    int b     = blockIdx.z;
    int mBase = blockIdx.x * 32;
    int cBase = blockIdx.y * 32;
    int tx = threadIdx.x & 31;
    int ty = threadIdx.x >> 5;

    #pragma unroll
    for (int i = 0; i < 4; i++) {
        int c = cBase + ty + i * 8;
        int m = mBase + tx;
        float v;
        if (c < CF) v = rf[((size_t)b * CF + c) * MM + m];
        else        v = rt[((size_t)b * CT + (c - CF)) * MM + m];
        tile[ty + i * 8][tx] = v;
    }
    __syncthreads();
    #pragma unroll
    for (int i = 0; i < 4; i++) {
        int m = mBase + ty + i * 8;
        int c = cBase + tx;
        g_featT[((size_t)b * MM + m) * CTOT + c] = tile[tx][ty + i * 8];
    }
}

// ---------------------------------------------------------------------------
// Weighted gather of 3 contiguous 384-float rows per query point (float4
// loads), staged through padded smem so [B,C,N] writes coalesce along n.
// ---------------------------------------------------------------------------
__global__ __launch_bounds__(256) void interp_kernel(float* __restrict__ out) {
    __shared__ float sacc[PTS * (CTOT + 1)];
    __shared__ int   sidx[PTS * 3];
    __shared__ float sw[PTS * 3];

    int tid = threadIdx.x;
    int blocksPerB = NN / PTS;
    int b  = blockIdx.x / blocksPerB;
    int n0 = (blockIdx.x % blocksPerB) * PTS;

    if (tid < PTS * 3) {
        size_t base = ((size_t)(b * NN + n0)) * 3;
        sidx[tid] = g_idx[base + tid];
        sw[tid]   = g_w[base + tid];
    }
    __syncthreads();

    const float4* ft = (const float4*)(g_featT + (size_t)b * MM * CTOT);
    const int R4 = CTOT / 4;

    for (int j = tid; j < PTS * R4; j += 256) {
        int nl = j / R4;
        int c4 = j - nl * R4;
        int q  = nl * 3;
        float w0 = sw[q], w1 = sw[q + 1], w2 = sw[q + 2];
        float4 a  = ft[(size_t)sidx[q]     * R4 + c4];
        float4 bv = ft[(size_t)sidx[q + 1] * R4 + c4];
        float4 cv = ft[(size_t)sidx[q + 2] * R4 + c4];
        float* dst = sacc + nl * (CTOT + 1) + c4 * 4;
        dst[0] = fmaf(w0, a.x, fmaf(w1, bv.x, w2 * cv.x));
        dst[1] = fmaf(w0, a.y, fmaf(w1, bv.y, w2 * cv.y));
        dst[2] = fmaf(w0, a.z, fmaf(w1, bv.z, w2 * cv.z));
        dst[3] = fmaf(w0, a.w, fmaf(w1, bv.w, w2 * cv.w));
    }
    __syncthreads();

    float* tout = out + (size_t)BB * 320 * NN;
    for (int j = tid; j < PTS * CTOT; j += 256) {
        int c  = j >> 4;
        int nl = j & 15;
        float v = sacc[nl * (CTOT + 1) + c];
        if (c < CF) out[((size_t)b * 320 + c) * NN + n0 + nl] = v;
        else        tout[((size_t)b * CT + (c - CF)) * NN + n0 + nl] = v;
    }
}

// ---------------------------------------------------------------------------
extern "C" void kernel_launch(void* const* d_in, const int* in_sizes, int n_in,
                              void* d_out, int out_size) {
    const float* coords = (const float*)d_in[0];   // [B, N, 3]
    const float* refc   = (const float*)d_in[1];   // [B, M, 3]
    const float* rf     = (const float*)d_in[2];   // [B, 256, M]
    const float* rt     = (const float*)d_in[3];   // [B, 128, M]
    const float* pf     = (const float*)d_in[4];   // [B, 64, N]
    float* out = (float*)d_out;

    zero_kernel<<<BB * GC / 256, 256>>>();
    count_kernel<<<(BB * (MM + NN) + 255) / 256, 256>>>(coords, refc);
    scan_kernel<<<BB * 2, 1024>>>();
    scatter_kernel<<<(BB * (MM + NN) + 255) / 256, 256>>>(coords, refc);
    knn_query_kernel<<<BB * NN / 128, 128>>>();

    dim3 tg(MM / 32, CTOT / 32, BB);
    transpose_kernel<<<tg, 256>>>(rf, rt);

    interp_kernel<<<BB * NN / PTS, 256>>>(out);

    for (int b = 0; b < BB; b++) {
        cudaMemcpyAsync(out + ((size_t)b * 320 + 256) * NN,
                        pf + (size_t)b * CP * NN,
                        (size_t)CP * NN * sizeof(float),
                        cudaMemcpyDeviceToDevice);
    }
}

// round 12
// speedup vs baseline: 1.9204x; 1.9204x over previous
#include <cuda_runtime.h>

#define BB   2
#define NN   16384
#define MM   4096
#define CF   256
#define CT   128
#define CP   64
#define CTOT 384
#define PTS  16
#define G    8
#define GC   (G * G * G)
#define HCELL 1.0f
#define ORG  (-4.0f)
#define INVH 1.0f

// ---- scratch (device globals; no allocation allowed) ----------------------
__device__ int    g_rcnt[BB][GC];
__device__ int    g_qcnt[BB][GC];
__device__ int    g_rstart[BB][GC + 1];
__device__ int    g_qstart[BB][GC + 1];
__device__ int    g_rcur[BB][GC];
__device__ int    g_qcur[BB][GC];
__device__ float4 g_rsort[BB * MM];
__device__ int    g_rid[BB * MM];
__device__ float4 g_qsort[BB * NN];
__device__ int    g_qid[BB * NN];
__device__ int    g_idx[BB * NN * 3];
__device__ float  g_w[BB * NN * 3];
__device__ float  g_featT[(size_t)BB * MM * CTOT];

__device__ __forceinline__ int cell1(float x) {
    int c = (int)floorf((x - ORG) * INVH);
    return min(max(c, 0), G - 1);
}

#define INS3(d0, d1, d2, i0, i1, i2, dv, iv)                                   \
    if (dv < d2) {                                                             \
        if (dv < d1) {                                                         \
            d2 = d1; i2 = i1;                                                  \
            if (dv < d0) { d1 = d0; i1 = i0; d0 = dv; i0 = iv; }               \
            else         { d1 = dv; i1 = iv; }                                 \
        } else { d2 = dv; i2 = iv; }                                           \
    }

// ---------------------------------------------------------------------------
__global__ __launch_bounds__(256) void zero_kernel() {
    int i = blockIdx.x * 256 + threadIdx.x;          // over BB*GC
    ((int*)g_rcnt)[i] = 0;
    ((int*)g_qcnt)[i] = 0;
}

__global__ __launch_bounds__(256) void count_kernel(const float* __restrict__ coords,
                                                    const float* __restrict__ refc) {
    int i = blockIdx.x * 256 + threadIdx.x;
    const int nref = BB * MM;
    if (i < nref) {
        int b = i / MM;
        const float* r = refc + (size_t)i * 3;
        int c = (cell1(r[2]) * G + cell1(r[1])) * G + cell1(r[0]);
        atomicAdd(&g_rcnt[b][c], 1);
    } else if (i < nref + BB * NN) {
        int j = i - nref;
        int b = j / NN;
        const float* p = coords + (size_t)j * 3;
        int c = (cell1(p[2]) * G + cell1(p[1])) * G + cell1(p[0]);
        atomicAdd(&g_qcnt[b][c], 1);
    }
}

// one block of 512 threads per (batch, type): exclusive scan of 512 counts
__global__ __launch_bounds__(512) void scan_kernel() {
    int type = blockIdx.x & 1, b = blockIdx.x >> 1;
    const int* cnt = type ? g_qcnt[b] : g_rcnt[b];
    int* start = type ? g_qstart[b] : g_rstart[b];
    int* cur   = type ? g_qcur[b]   : g_rcur[b];

    int t = threadIdx.x, lane = t & 31, w = t >> 5;   // 16 warps
    int v = cnt[t];
    int inc = v;
    #pragma unroll
    for (int off = 1; off < 32; off <<= 1) {
        int u = __shfl_up_sync(0xffffffffu, inc, off);
        if (lane >= off) inc += u;
    }
    __shared__ int wsum[16];
    if (lane == 31) wsum[w] = inc;
    __syncthreads();
    if (t < 16) {
        int x = wsum[t];
        #pragma unroll
        for (int off = 1; off < 16; off <<= 1) {
            int u = __shfl_up_sync(0x0000ffffu, x, off);
            if (t >= off) x += u;
        }
        wsum[t] = x;
    }
    __syncthreads();
    int excl = inc - v + (w ? wsum[w - 1] : 0);
    start[t] = excl;
    cur[t]   = excl;
    if (t == 511) start[GC] = excl + v;
}

__global__ __launch_bounds__(256) void scatter_kernel(const float* __restrict__ coords,
                                                      const float* __restrict__ refc) {
    int i = blockIdx.x * 256 + threadIdx.x;
    const int nref = BB * MM;
    if (i < nref) {
        int b = i / MM;
        const float* r = refc + (size_t)i * 3;
        float x = r[0], y = r[1], z = r[2];
        int c = (cell1(z) * G + cell1(y)) * G + cell1(x);
        int pos = atomicAdd(&g_rcur[b][c], 1);
        g_rsort[b * MM + pos] = make_float4(x, y, z, x * x + y * y + z * z);
        g_rid[b * MM + pos]   = i - b * MM;
    } else if (i < nref + BB * NN) {
        int j = i - nref;
        int b = j / NN;
        const float* p = coords + (size_t)j * 3;
        float x = p[0], y = p[1], z = p[2];
        int c = (cell1(z) * G + cell1(y)) * G + cell1(x);
        int pos = atomicAdd(&g_qcur[b][c], 1);
        g_qsort[b * NN + pos] = make_float4(x, y, z, x * x + y * y + z * z);
        g_qid[b * NN + pos]   = j - b * NN;
    }
}

// ---------------------------------------------------------------------------
// Exact 3-NN by expanding Chebyshev rings over the 8^3 ref grid. One (cell-
// sorted) query per lane; terminate when the explored box's face distance
// beats the current 3rd-NN distance. Out-of-grid cells are empty = explored;
// clamped points lie outside their border cell's box, so the face-distance
// lower bound stays valid and exactness holds (loop to r=G covers all cells).
// ---------------------------------------------------------------------------
__global__ __launch_bounds__(128) void knn_query_kernel() {
    int id = blockIdx.x * 128 + threadIdx.x;     // over BB*NN sorted queries
    int b = id / NN;

    float4 q = g_qsort[id];
    float px = q.x, py = q.y, pz = q.z, pp = q.w;
    float px2 = -2.0f * px, py2 = -2.0f * py, pz2 = -2.0f * pz;
    int cx = cell1(px), cy = cell1(py), cz = cell1(pz);

    float d0 = 1e30f, d1 = 1e30f, d2 = 1e30f;    // shifted: |r|^2 - 2 p.r
    int   i0 = 0, i1 = 0, i2 = 0;

    const int*    cs = g_rstart[b];
    const float4* rs = g_rsort + b * MM;

    for (int r = 0; r <= G; r++) {
        for (int dz = -r; dz <= r; dz++) {
            int z = cz + dz;
            if (z < 0 || z >= G) continue;
            bool zface = (dz == -r) || (dz == r);
            for (int dy = -r; dy <= r; dy++) {
                int y = cy + dy;
                if (y < 0 || y >= G) continue;
                bool face = zface || (dy == -r) || (dy == r);
                int step = face ? 1 : (r > 0 ? 2 * r : 1);
                for (int dx = -r; dx <= r; dx += step) {
                    int x = cx + dx;
                    if (x < 0 || x >= G) continue;
                    int cid = (z * G + y) * G + x;
                    int s = cs[cid], e = cs[cid + 1];
                    for (int j = s; j < e; j++) {
                        float4 rr = rs[j];
                        float dp = fmaf(rr.x, px2, fmaf(rr.y, py2, fmaf(rr.z, pz2, rr.w)));
                        INS3(d0, d1, d2, i0, i1, i2, dp, j);
                    }
                }
            }
        }
        // explored box after ring r = [(c-r)h+ORG, (c+r+1)h+ORG]^3
        float mx = fminf(px - ((cx - r) * HCELL + ORG), ((cx + r + 1) * HCELL + ORG) - px);
        float my = fminf(py - ((cy - r) * HCELL + ORG), ((cy + r + 1) * HCELL + ORG) - py);
        float mz = fminf(pz - ((cz - r) * HCELL + ORG), ((cz + r + 1) * HCELL + ORG) - pz);
        float margin = fminf(mx, fminf(my, mz));
        if (margin > 0.0f && margin * margin >= d2 + pp) break;
    }

    float t0 = d0 + pp, t1 = d1 + pp, t2 = d2 + pp;
    float w0 = 1.0f / (t0 + 1e-8f);
    float w1 = 1.0f / (t1 + 1e-8f);
    float w2 = 1.0f / (t2 + 1e-8f);
    float inv = 1.0f / (w0 + w1 + w2);

    int outp = b * NN + g_qid[id];               // original query position
    size_t o = (size_t)outp * 3;
    g_w[o]     = w0 * inv;
    g_w[o + 1] = w1 * inv;
    g_w[o + 2] = w2 * inv;
    g_idx[o]     = g_rid[b * MM + i0];
    g_idx[o + 1] = g_rid[b * MM + i1];
    g_idx[o + 2] = g_rid[b * MM + i2];
}

// ---------------------------------------------------------------------------
// Transpose ref_features + ref_t_embed into channel-contiguous [B, M, 384].
// ---------------------------------------------------------------------------
__global__ __launch_bounds__(256) void transpose_kernel(const float* __restrict__ rf,
                                                        const float* __restrict__ rt) {
    __shared__ float tile[32][33];
    int b     = blockIdx.z;
    int mBase = blockIdx.x * 32;
    int cBase = blockIdx.y * 32;
    int tx = threadIdx.x & 31;
    int ty = threadIdx.x >> 5;

    #pragma unroll
    for (int i = 0; i < 4; i++) {
        int c = cBase + ty + i * 8;
        int m = mBase + tx;
        float v;
        if (c < CF) v = rf[((size_t)b * CF + c) * MM + m];
        else        v = rt[((size_t)b * CT + (c - CF)) * MM + m];
        tile[ty + i * 8][tx] = v;
    }
    __syncthreads();
    #pragma unroll
    for (int i = 0; i < 4; i++) {
        int m = mBase + ty + i * 8;
        int c = cBase + tx;
        g_featT[((size_t)b * MM + m) * CTOT + c] = tile[tx][ty + i * 8];
    }
}

// ---------------------------------------------------------------------------
// Weighted gather of 3 contiguous 384-float rows per query point (float4
// loads), staged through padded smem so [B,C,N] writes coalesce along n.
// ---------------------------------------------------------------------------
__global__ __launch_bounds__(256) void interp_kernel(float* __restrict__ out) {
    __shared__ float sacc[PTS * (CTOT + 1)];
    __shared__ int   sidx[PTS * 3];
    __shared__ float sw[PTS * 3];

    int tid = threadIdx.x;
    int blocksPerB = NN / PTS;
    int b  = blockIdx.x / blocksPerB;
    int n0 = (blockIdx.x % blocksPerB) * PTS;

    if (tid < PTS * 3) {
        size_t base = ((size_t)(b * NN + n0)) * 3;
        sidx[tid] = g_idx[base + tid];
        sw[tid]   = g_w[base + tid];
    }
    __syncthreads();

    const float4* ft = (const float4*)(g_featT + (size_t)b * MM * CTOT);
    const int R4 = CTOT / 4;

    for (int j = tid; j < PTS * R4; j += 256) {
        int nl = j / R4;
        int c4 = j - nl * R4;
        int q  = nl * 3;
        float w0 = sw[q], w1 = sw[q + 1], w2 = sw[q + 2];
        float4 a  = ft[(size_t)sidx[q]     * R4 + c4];
        float4 bv = ft[(size_t)sidx[q + 1] * R4 + c4];
        float4 cv = ft[(size_t)sidx[q + 2] * R4 + c4];
        float* dst = sacc + nl * (CTOT + 1) + c4 * 4;
        dst[0] = fmaf(w0, a.x, fmaf(w1, bv.x, w2 * cv.x));
        dst[1] = fmaf(w0, a.y, fmaf(w1, bv.y, w2 * cv.y));
        dst[2] = fmaf(w0, a.z, fmaf(w1, bv.z, w2 * cv.z));
        dst[3] = fmaf(w0, a.w, fmaf(w1, bv.w, w2 * cv.w));
    }
    __syncthreads();

    float* tout = out + (size_t)BB * 320 * NN;
    for (int j = tid; j < PTS * CTOT; j += 256) {
        int c  = j >> 4;
        int nl = j & 15;
        float v = sacc[nl * (CTOT + 1) + c];
        if (c < CF) out[((size_t)b * 320 + c) * NN + n0 + nl] = v;
        else        tout[((size_t)b * CT + (c - CF)) * NN + n0 + nl] = v;
    }
}

// ---------------------------------------------------------------------------
extern "C" void kernel_launch(void* const* d_in, const int* in_sizes, int n_in,
                              void* d_out, int out_size) {
    const float* coords = (const float*)d_in[0];   // [B, N, 3]
    const float* refc   = (const float*)d_in[1];   // [B, M, 3]
    const float* rf     = (const float*)d_in[2];   // [B, 256, M]
    const float* rt     = (const float*)d_in[3];   // [B, 128, M]
    const float* pf     = (const float*)d_in[4];   // [B, 64, N]
    float* out = (float*)d_out;

    zero_kernel<<<BB * GC / 256, 256>>>();
    count_kernel<<<(BB * (MM + NN) + 255) / 256, 256>>>(coords, refc);
    scan_kernel<<<BB * 2, 512>>>();
    scatter_kernel<<<(BB * (MM + NN) + 255) / 256, 256>>>(coords, refc);
    knn_query_kernel<<<BB * NN / 128, 128>>>();

    dim3 tg(MM / 32, CTOT / 32, BB);
    transpose_kernel<<<tg, 256>>>(rf, rt);

    interp_kernel<<<BB * NN / PTS, 256>>>(out);

    for (int b = 0; b < BB; b++) {
        cudaMemcpyAsync(out + ((size_t)b * 320 + 256) * NN,
                        pf + (size_t)b * CP * NN,
                        (size_t)CP * NN * sizeof(float),
                        cudaMemcpyDeviceToDevice);
    }
}

// round 15
// speedup vs baseline: 5.3914x; 2.8075x over previous
#include <cuda_runtime.h>

#define BB   2
#define NN   16384
#define MM   4096
#define CF   256
#define CT   128
#define CP   64
#define CTOT 384
#define SEG  4
#define SEGM (MM / SEG)   // 1024
#define PTS  16

// ---- scratch (device globals; no allocation allowed) ----------------------
__device__ float g_pd[BB * NN * SEG * 3];   // partial top-3 shifted distances
__device__ int   g_pi[BB * NN * SEG * 3];   // partial top-3 indices
__device__ float g_featT[(size_t)BB * MM * CTOT];

#define INS3(d0, d1, d2, i0, i1, i2, dv, iv)                                   \
    if (dv < d2) {                                                             \
        if (dv < d1) {                                                         \
            d2 = d1; i2 = i1;                                                  \
            if (dv < d0) { d1 = d0; i1 = i0; d0 = dv; i0 = iv; }               \
            else         { d1 = dv; i1 = iv; }                                 \
        } else { d2 = dv; i2 = iv; }                                           \
    }

// ---------------------------------------------------------------------------
// Kernel 1: partial 3-NN (R5-proven config). One query point per lane; all
// lanes scan the same candidate (broadcast LDS.128). M split across SEG
// blocks per point-group for occupancy. Shifted space d' = |r|^2 - 2 p.r.
// ---------------------------------------------------------------------------
__global__ __launch_bounds__(128) void knn_partial_kernel(const float* __restrict__ coords,
                                                          const float* __restrict__ refc) {
    __shared__ float4 sref[SEGM];   // {rx, ry, rz, |r|^2}  (16 KB)

    int tid  = threadIdx.x;
    int bid  = blockIdx.x;
    int seg  = bid & (SEG - 1);
    int rest = bid >> 2;                 // BB * 128 point-groups
    int b    = rest >> 7;
    int pt   = ((rest & 127) << 7) + tid;

    const float* cp = coords + ((size_t)(b * NN + pt)) * 3;
    float px = cp[0], py = cp[1], pz = cp[2];
    float px2 = -2.0f * px, py2 = -2.0f * py, pz2 = -2.0f * pz;

    const float* rb = refc + ((size_t)b * MM + seg * SEGM) * 3;
    for (int m = tid; m < SEGM; m += 128) {
        const float* r = rb + (size_t)m * 3;
        float rx = r[0], ry = r[1], rz = r[2];
        sref[m] = make_float4(rx, ry, rz, rx * rx + ry * ry + rz * rz);
    }
    __syncthreads();

    float d0 = 1e30f, d1 = 1e30f, d2 = 1e30f;   // shifted-space distances
    int   i0 = 0, i1 = 0, i2 = 0;
    int   gbase = seg * SEGM;

    #pragma unroll 8
    for (int m = 0; m < SEGM; m++) {
        float4 r = sref[m];
        float dp = fmaf(r.x, px2, fmaf(r.y, py2, fmaf(r.z, pz2, r.w)));
        if (dp < d2) {
            int gm = gbase + m;
            if (dp < d1) {
                d2 = d1; i2 = i1;
                if (dp < d0) { d1 = d0; i1 = i0; d0 = dp; i0 = gm; }
                else         { d1 = dp; i1 = gm; }
            } else { d2 = dp; i2 = gm; }
        }
    }

    size_t base = (((size_t)(b * NN + pt)) * SEG + seg) * 3;
    g_pd[base]     = d0;  g_pi[base]     = i0;
    g_pd[base + 1] = d1;  g_pi[base + 1] = i1;
    g_pd[base + 2] = d2;  g_pi[base + 2] = i2;
}

// ---------------------------------------------------------------------------
// Kernel 2: transpose ref_features + ref_t_embed into [B, M, 384].
// ---------------------------------------------------------------------------
__global__ __launch_bounds__(256) void transpose_kernel(const float* __restrict__ rf,
                                                        const float* __restrict__ rt) {
    __shared__ float tile[32][33];
    int b     = blockIdx.z;
    int mBase = blockIdx.x * 32;
    int cBase = blockIdx.y * 32;
    int tx = threadIdx.x & 31;
    int ty = threadIdx.x >> 5;

    #pragma unroll
    for (int i = 0; i < 4; i++) {
        int c = cBase + ty + i * 8;
        int m = mBase + tx;
        float v;
        if (c < CF) v = rf[((size_t)b * CF + c) * MM + m];
        else        v = rt[((size_t)b * CT + (c - CF)) * MM + m];
        tile[ty + i * 8][tx] = v;
    }
    __syncthreads();
    #pragma unroll
    for (int i = 0; i < 4; i++) {
        int m = mBase + ty + i * 8;
        int c = cBase + tx;
        g_featT[((size_t)b * MM + m) * CTOT + c] = tile[tx][ty + i * 8];
    }
}

// ---------------------------------------------------------------------------
// Kernel 3 (fused): per-point partial merge (float, exact R5 math) +
// inverse-distance weights + weighted float4 gather + transposed coalesced
// writes + points_features skip-copy.
// ---------------------------------------------------------------------------
__global__ __launch_bounds__(256) void interp_kernel(const float* __restrict__ coords,
                                                     const float* __restrict__ pf,
                                                     float* __restrict__ out) {
    __shared__ float sacc[PTS * (CTOT + 1)];
    __shared__ int   sidx[PTS * 3];
    __shared__ float sw[PTS * 3];

    int tid = threadIdx.x;
    int blocksPerB = NN / PTS;           // 1024
    int b  = blockIdx.x / blocksPerB;
    int n0 = (blockIdx.x % blocksPerB) * PTS;

    // merge SEG partial top-3 lists per point (same math as R5's merge kernel)
    if (tid < PTS) {
        int pt = n0 + tid;
        size_t pbase = ((size_t)(b * NN + pt)) * SEG * 3;

        float d0 = 1e30f, d1 = 1e30f, d2 = 1e30f;
        int   i0 = 0, i1 = 0, i2 = 0;
        #pragma unroll
        for (int s = 0; s < SEG * 3; s++) {
            float dv = g_pd[pbase + s];
            int   iv = g_pi[pbase + s];
            INS3(d0, d1, d2, i0, i1, i2, dv, iv);
        }

        const float* cp = coords + ((size_t)(b * NN + pt)) * 3;
        float px = cp[0], py = cp[1], pz = cp[2];
        float pp = px * px + py * py + pz * pz;
        d0 += pp; d1 += pp; d2 += pp;

        float w0 = 1.0f / (d0 + 1e-8f);
        float w1 = 1.0f / (d1 + 1e-8f);
        float w2 = 1.0f / (d2 + 1e-8f);
        float inv = 1.0f / (w0 + w1 + w2);
        sw[tid * 3]     = w0 * inv;
        sw[tid * 3 + 1] = w1 * inv;
        sw[tid * 3 + 2] = w2 * inv;
        sidx[tid * 3]     = i0;
        sidx[tid * 3 + 1] = i1;
        sidx[tid * 3 + 2] = i2;
    }
    __syncthreads();

    const float4* ft = (const float4*)(g_featT + (size_t)b * MM * CTOT);
    const int R4 = CTOT / 4;             // 96

    for (int j = tid; j < PTS * R4; j += 256) {
        int nl = j / R4;
        int c4 = j - nl * R4;
        int q  = nl * 3;
        float w0 = sw[q], w1 = sw[q + 1], w2 = sw[q + 2];
        float4 a  = ft[(size_t)sidx[q]     * R4 + c4];
        float4 bv = ft[(size_t)sidx[q + 1] * R4 + c4];
        float4 cv = ft[(size_t)sidx[q + 2] * R4 + c4];
        float* dst = sacc + nl * (CTOT + 1) + c4 * 4;
        dst[0] = fmaf(w0, a.x, fmaf(w1, bv.x, w2 * cv.x));
        dst[1] = fmaf(w0, a.y, fmaf(w1, bv.y, w2 * cv.y));
        dst[2] = fmaf(w0, a.z, fmaf(w1, bv.z, w2 * cv.z));
        dst[3] = fmaf(w0, a.w, fmaf(w1, bv.w, w2 * cv.w));
    }
    __syncthreads();

    float* tout = out + (size_t)BB * 320 * NN;   // t_embed block after features
    for (int j = tid; j < PTS * CTOT; j += 256) {
        int c  = j >> 4;
        int nl = j & 15;
        float v = sacc[nl * (CTOT + 1) + c];
        if (c < CF) out[((size_t)b * 320 + c) * NN + n0 + nl] = v;
        else        tout[((size_t)b * CT + (c - CF)) * NN + n0 + nl] = v;
    }

    // skip-feature concat: channels 256..319 = points_features
    for (int j = tid; j < PTS * CP; j += 256) {
        int c  = j >> 4;
        int nl = j & 15;
        out[((size_t)b * 320 + 256 + c) * NN + n0 + nl] =
            pf[((size_t)b * CP + c) * NN + n0 + nl];
    }
}

// ---------------------------------------------------------------------------
extern "C" void kernel_launch(void* const* d_in, const int* in_sizes, int n_in,
                              void* d_out, int out_size) {
    const float* coords = (const float*)d_in[0];   // [B, N, 3]
    const float* refc   = (const float*)d_in[1];   // [B, M, 3]
    const float* rf     = (const float*)d_in[2];   // [B, 256, M]
    const float* rt     = (const float*)d_in[3];   // [B, 128, M]
    const float* pf     = (const float*)d_in[4];   // [B, 64, N]
    float* out = (float*)d_out;

    knn_partial_kernel<<<BB * (NN / 128) * SEG, 128>>>(coords, refc);

    dim3 tg(MM / 32, CTOT / 32, BB);
    transpose_kernel<<<tg, 256>>>(rf, rt);

    interp_kernel<<<BB * NN / PTS, 256>>>(coords, pf, out);
}

// round 16
// speedup vs baseline: 5.4356x; 1.0082x over previous
#include <cuda_runtime.h>

#define BB   2
#define NN   16384
#define MM   4096
#define CF   256
#define CT   128
#define CP   64
#define CTOT 384
#define SEG  8
#define SEGM (MM / SEG)   // 512
#define PTS  16

// ---- scratch (device globals; no allocation allowed) ----------------------
__device__ float g_pd[BB * NN * SEG * 3];   // partial top-3 shifted distances
__device__ int   g_pi[BB * NN * SEG * 3];   // partial top-3 indices
__device__ float g_featT[(size_t)BB * MM * CTOT];

// guarded insert: one divergent region, flat selects inside (== INS3 result)
#define FINS3(d0, d1, d2, i0, i1, i2, dv, iv)                                  \
    if (dv < d2) {                                                             \
        bool _b0 = dv < d0, _b1 = dv < d1;                                     \
        d2 = _b1 ? d1 : dv;              i2 = _b1 ? i1 : iv;                   \
        d1 = _b0 ? d0 : (_b1 ? dv : d1); i1 = _b0 ? i0 : (_b1 ? iv : i1);      \
        d0 = _b0 ? dv : d0;              i0 = _b0 ? iv : i0;                   \
    }

#define INS3(d0, d1, d2, i0, i1, i2, dv, iv)                                   \
    if (dv < d2) {                                                             \
        if (dv < d1) {                                                         \
            d2 = d1; i2 = i1;                                                  \
            if (dv < d0) { d1 = d0; i1 = i0; d0 = dv; i0 = iv; }               \
            else         { d1 = dv; i1 = iv; }                                 \
        } else { d2 = dv; i2 = iv; }                                           \
    }

// ---------------------------------------------------------------------------
// Kernel 1: partial 3-NN. TWO query points per lane (amortizes the broadcast
// LDS.128, loop overhead and branch scaffolding); all lanes scan the same
// candidate. M split across SEG blocks per 256-point group. Shifted space
// d' = |r|^2 - 2 p.r (exact same comparison math as the R5-proven kernel).
// ---------------------------------------------------------------------------
__global__ __launch_bounds__(128) void knn_partial_kernel(const float* __restrict__ coords,
                                                          const float* __restrict__ refc) {
    __shared__ float4 sref[SEGM];   // {rx, ry, rz, |r|^2}  (8 KB)

    int tid  = threadIdx.x;
    int bid  = blockIdx.x;
    int seg  = bid & (SEG - 1);
    int rest = bid >> 3;                 // BB * 64 groups of 256 points
    int b    = rest >> 6;
    int base = (rest & 63) << 8;
    int ptA  = base + tid;
    int ptB  = base + 128 + tid;

    const float* cA = coords + ((size_t)(b * NN + ptA)) * 3;
    const float* cB = coords + ((size_t)(b * NN + ptB)) * 3;
    float ax2 = -2.0f * cA[0], ay2 = -2.0f * cA[1], az2 = -2.0f * cA[2];
    float bx2 = -2.0f * cB[0], by2 = -2.0f * cB[1], bz2 = -2.0f * cB[2];

    const float* rb = refc + ((size_t)b * MM + seg * SEGM) * 3;
    for (int m = tid; m < SEGM; m += 128) {
        const float* r = rb + (size_t)m * 3;
        float rx = r[0], ry = r[1], rz = r[2];
        sref[m] = make_float4(rx, ry, rz, rx * rx + ry * ry + rz * rz);
    }
    __syncthreads();

    float da0 = 1e30f, da1 = 1e30f, da2 = 1e30f;
    int   ia0 = 0, ia1 = 0, ia2 = 0;
    float db0 = 1e30f, db1 = 1e30f, db2 = 1e30f;
    int   ib0 = 0, ib1 = 0, ib2 = 0;
    int   gbase = seg * SEGM;

    #pragma unroll 8
    for (int m = 0; m < SEGM; m++) {
        float4 r = sref[m];
        float dA = fmaf(r.x, ax2, fmaf(r.y, ay2, fmaf(r.z, az2, r.w)));
        float dB = fmaf(r.x, bx2, fmaf(r.y, by2, fmaf(r.z, bz2, r.w)));
        int gm = gbase + m;
        FINS3(da0, da1, da2, ia0, ia1, ia2, dA, gm);
        FINS3(db0, db1, db2, ib0, ib1, ib2, dB, gm);
    }

    size_t oA = (((size_t)(b * NN + ptA)) * SEG + seg) * 3;
    size_t oB = (((size_t)(b * NN + ptB)) * SEG + seg) * 3;
    g_pd[oA] = da0;  g_pi[oA] = ia0;
    g_pd[oA + 1] = da1;  g_pi[oA + 1] = ia1;
    g_pd[oA + 2] = da2;  g_pi[oA + 2] = ia2;
    g_pd[oB] = db0;  g_pi[oB] = ib0;
    g_pd[oB + 1] = db1;  g_pi[oB + 1] = ib1;
    g_pd[oB + 2] = db2;  g_pi[oB + 2] = ib2;
}

// ---------------------------------------------------------------------------
// Kernel 2: transpose ref_features + ref_t_embed into [B, M, 384].
// ---------------------------------------------------------------------------
__global__ __launch_bounds__(256) void transpose_kernel(const float* __restrict__ rf,
                                                        const float* __restrict__ rt) {
    __shared__ float tile[32][33];
    int b     = blockIdx.z;
    int mBase = blockIdx.x * 32;
    int cBase = blockIdx.y * 32;
    int tx = threadIdx.x & 31;
    int ty = threadIdx.x >> 5;

    #pragma unroll
    for (int i = 0; i < 4; i++) {
        int c = cBase + ty + i * 8;
        int m = mBase + tx;
        float v;
        if (c < CF) v = rf[((size_t)b * CF + c) * MM + m];
        else        v = rt[((size_t)b * CT + (c - CF)) * MM + m];
        tile[ty + i * 8][tx] = v;
    }
    __syncthreads();
    #pragma unroll
    for (int i = 0; i < 4; i++) {
        int m = mBase + ty + i * 8;
        int c = cBase + tx;
        g_featT[((size_t)b * MM + m) * CTOT + c] = tile[tx][ty + i * 8];
    }
}

// ---------------------------------------------------------------------------
// Kernel 3 (fused): per-point partial merge (float, exact R5 math) +
// inverse-distance weights + weighted float4 gather + transposed coalesced
// writes + points_features skip-copy.
// ---------------------------------------------------------------------------
__global__ __launch_bounds__(256) void interp_kernel(const float* __restrict__ coords,
                                                     const float* __restrict__ pf,
                                                     float* __restrict__ out) {
    __shared__ float sacc[PTS * (CTOT + 1)];
    __shared__ int   sidx[PTS * 3];
    __shared__ float sw[PTS * 3];

    int tid = threadIdx.x;
    int blocksPerB = NN / PTS;           // 1024
    int b  = blockIdx.x / blocksPerB;
    int n0 = (blockIdx.x % blocksPerB) * PTS;

    if (tid < PTS) {
        int pt = n0 + tid;
        size_t pbase = ((size_t)(b * NN + pt)) * SEG * 3;

        float d0 = 1e30f, d1 = 1e30f, d2 = 1e30f;
        int   i0 = 0, i1 = 0, i2 = 0;
        #pragma unroll
        for (int s = 0; s < SEG * 3; s++) {
            float dv = g_pd[pbase + s];
            int   iv = g_pi[pbase + s];
            INS3(d0, d1, d2, i0, i1, i2, dv, iv);
        }

        const float* cp = coords + ((size_t)(b * NN + pt)) * 3;
        float px = cp[0], py = cp[1], pz = cp[2];
        float pp = px * px + py * py + pz * pz;
        d0 += pp; d1 += pp; d2 += pp;

        float w0 = 1.0f / (d0 + 1e-8f);
        float w1 = 1.0f / (d1 + 1e-8f);
        float w2 = 1.0f / (d2 + 1e-8f);
        float inv = 1.0f / (w0 + w1 + w2);
        sw[tid * 3]     = w0 * inv;
        sw[tid * 3 + 1] = w1 * inv;
        sw[tid * 3 + 2] = w2 * inv;
        sidx[tid * 3]     = i0;
        sidx[tid * 3 + 1] = i1;
        sidx[tid * 3 + 2] = i2;
    }
    __syncthreads();

    const float4* ft = (const float4*)(g_featT + (size_t)b * MM * CTOT);
    const int R4 = CTOT / 4;             // 96

    for (int j = tid; j < PTS * R4; j += 256) {
        int nl = j / R4;
        int c4 = j - nl * R4;
        int q  = nl * 3;
        float w0 = sw[q], w1 = sw[q + 1], w2 = sw[q + 2];
        float4 a  = ft[(size_t)sidx[q]     * R4 + c4];
        float4 bv = ft[(size_t)sidx[q + 1] * R4 + c4];
        float4 cv = ft[(size_t)sidx[q + 2] * R4 + c4];
        float* dst = sacc + nl * (CTOT + 1) + c4 * 4;
        dst[0] = fmaf(w0, a.x, fmaf(w1, bv.x, w2 * cv.x));
        dst[1] = fmaf(w0, a.y, fmaf(w1, bv.y, w2 * cv.y));
        dst[2] = fmaf(w0, a.z, fmaf(w1, bv.z, w2 * cv.z));
        dst[3] = fmaf(w0, a.w, fmaf(w1, bv.w, w2 * cv.w));
    }
    __syncthreads();

    float* tout = out + (size_t)BB * 320 * NN;   // t_embed block after features
    for (int j = tid; j < PTS * CTOT; j += 256) {
        int c  = j >> 4;
        int nl = j & 15;
        float v = sacc[nl * (CTOT + 1) + c];
        if (c < CF) out[((size_t)b * 320 + c) * NN + n0 + nl] = v;
        else        tout[((size_t)b * CT + (c - CF)) * NN + n0 + nl] = v;
    }

    // skip-feature concat: channels 256..319 = points_features
    for (int j = tid; j < PTS * CP; j += 256) {
        int c  = j >> 4;
        int nl = j & 15;
        out[((size_t)b * 320 + 256 + c) * NN + n0 + nl] =
            pf[((size_t)b * CP + c) * NN + n0 + nl];
    }
}

// ---------------------------------------------------------------------------
extern "C" void kernel_launch(void* const* d_in, const int* in_sizes, int n_in,
                              void* d_out, int out_size) {
    const float* coords = (const float*)d_in[0];   // [B, N, 3]
    const float* refc   = (const float*)d_in[1];   // [B, M, 3]
    const float* rf     = (const float*)d_in[2];   // [B, 256, M]
    const float* rt     = (const float*)d_in[3];   // [B, 128, M]
    const float* pf     = (const float*)d_in[4];   // [B, 64, N]
    float* out = (float*)d_out;

    knn_partial_kernel<<<BB * (NN / 256) * SEG, 128>>>(coords, refc);

    dim3 tg(MM / 32, CTOT / 32, BB);
    transpose_kernel<<<tg, 256>>>(rf, rt);

    interp_kernel<<<BB * NN / PTS, 256>>>(coords, pf, out);
}